// round 5
// baseline (speedup 1.0000x reference)
#include <cuda_runtime.h>
#include <cuda_bf16.h>
#include <cstdint>

// Shapes (fixed): x (2048,4096) fp32, values (1024,64,64) fp32, bias (4096,),
// block_rows/cols (1024,) int32 in [0,64), out (2048,4096) fp32.
#define KDIM  4096
#define MDIM  4096
#define TTOK  2048
#define NBMAX 1024
#define MT    128            // tokens per CTA
#define NT    64             // out features per CTA (one row block)

// Half-block staging: K=32 per stage, row pitch 40 bf16 = 80 B (16B multiple,
// and 80*r mod 128 distinct for r=0..7 -> ldmatrix conflict-free).
#define PITCHB  80
#define XB      (128 * PITCHB)        // 10240 per array
#define VB      (64  * PITCHB)        // 5120  per array
#define STAGE   (2 * XB + 2 * VB)     // 30720
#define NSTG    3
#define SMEM_TOTAL (NSTG * STAGE)     // 92160 -> 2 CTAs/SM

// ---- device scratch (static globals; no allocations allowed) ----
__device__ __nv_bfloat16 g_xhi[TTOK * KDIM];
__device__ __nv_bfloat16 g_xlo[TTOK * KDIM];
__device__ __nv_bfloat16 g_vhi[NBMAX * 64 * 64];
__device__ __nv_bfloat16 g_vlo[NBMAX * 64 * 64];
__device__ int g_row_list[64 * NBMAX];
__device__ int g_row_cnt[64];
__device__ int g_row_order[64];

// ---- PTX helpers (baseline sm_80+ features only) ----
__device__ __forceinline__ uint32_t smem_u32(const void* p) {
    uint32_t a;
    asm("{ .reg .u64 t; cvta.to.shared.u64 t, %1; cvt.u32.u64 %0, t; }" : "=r"(a) : "l"(p));
    return a;
}
__device__ __forceinline__ void cp_async16(uint32_t saddr, const void* gaddr) {
    asm volatile("cp.async.cg.shared.global [%0], [%1], 16;" :: "r"(saddr), "l"(gaddr));
}
#define CP_COMMIT() asm volatile("cp.async.commit_group;" ::: "memory")
#define CP_WAIT(n)  asm volatile("cp.async.wait_group %0;" :: "n"(n) : "memory")

__device__ __forceinline__ void ldsm_x4(uint32_t* r, uint32_t addr) {
    asm volatile("ldmatrix.sync.aligned.m8n8.x4.shared.b16 {%0,%1,%2,%3}, [%4];"
                 : "=r"(r[0]), "=r"(r[1]), "=r"(r[2]), "=r"(r[3]) : "r"(addr));
}
__device__ __forceinline__ void mma_bf16(float* d, const uint32_t* a, uint32_t b0, uint32_t b1) {
    asm volatile(
        "mma.sync.aligned.m16n8k16.row.col.f32.bf16.bf16.f32 "
        "{%0,%1,%2,%3}, {%4,%5,%6,%7}, {%8,%9}, {%0,%1,%2,%3};"
        : "+f"(d[0]), "+f"(d[1]), "+f"(d[2]), "+f"(d[3])
        : "r"(a[0]), "r"(a[1]), "r"(a[2]), "r"(a[3]), "r"(b0), "r"(b1));
}

__device__ __forceinline__ float gelu_tanh(float v) {
    float inner = 0.7978845608f * (v + 0.044715f * v * v * v);
    return 0.5f * v * (1.0f + tanhf(inner));
}

// ---------------------------------------------------------------------------
// Pre-pass 1: fp32 -> bf16 hi/lo split (which=0 -> x, 1 -> values)
// ---------------------------------------------------------------------------
__global__ void __launch_bounds__(256) convert_split_kernel(
    const float* __restrict__ src, int n4, int which)
{
    uint2* h2 = (uint2*)(which ? g_vhi : g_xhi);
    uint2* l2 = (uint2*)(which ? g_vlo : g_xlo);
    const float4* s4 = (const float4*)src;
    int stride = gridDim.x * blockDim.x;
    for (int i = blockIdx.x * blockDim.x + threadIdx.x; i < n4; i += stride) {
        float4 v = s4[i];
        __nv_bfloat16 hx = __float2bfloat16_rn(v.x);
        __nv_bfloat16 hy = __float2bfloat16_rn(v.y);
        __nv_bfloat16 hz = __float2bfloat16_rn(v.z);
        __nv_bfloat16 hw = __float2bfloat16_rn(v.w);
        __nv_bfloat16 lx = __float2bfloat16_rn(v.x - __bfloat162float(hx));
        __nv_bfloat16 ly = __float2bfloat16_rn(v.y - __bfloat162float(hy));
        __nv_bfloat16 lz = __float2bfloat16_rn(v.z - __bfloat162float(hz));
        __nv_bfloat16 lw = __float2bfloat16_rn(v.w - __bfloat162float(hw));
        __nv_bfloat162 p0{hx, hy}, p1{hz, hw}, q0{lx, ly}, q1{lz, lw};
        uint2 H{*(uint32_t*)&p0, *(uint32_t*)&p1};
        uint2 L{*(uint32_t*)&q0, *(uint32_t*)&q1};
        h2[i] = H;
        l2[i] = L;
    }
}

// ---------------------------------------------------------------------------
// Pre-pass 2: per-row compacted block lists (stable order -> deterministic)
// ---------------------------------------------------------------------------
__global__ void __launch_bounds__(32) build_lists_kernel(
    const int* __restrict__ brows, int nb)
{
    int r = blockIdx.x, lane = threadIdx.x, cnt = 0;
    for (int base = 0; base < nb; base += 32) {
        int n = base + lane;
        int row = (n < nb) ? brows[n] : -1;
        unsigned m = __ballot_sync(0xFFFFFFFFu, row == r);
        if (row == r)
            g_row_list[r * NBMAX + cnt + __popc(m & ((1u << lane) - 1u))] = n;
        cnt += __popc(m);
    }
    if (lane == 0) g_row_cnt[r] = cnt;
}

// Pre-pass 3: LPT order — rows sorted by cnt descending (stable, deterministic)
__global__ void sort_rows_kernel()
{
    if (threadIdx.x != 0 || blockIdx.x != 0) return;
    int ord[64];
    #pragma unroll
    for (int i = 0; i < 64; i++) ord[i] = i;
    for (int i = 0; i < 63; i++) {
        int best = i;
        for (int j = i + 1; j < 64; j++)
            if (g_row_cnt[ord[j]] > g_row_cnt[ord[best]]) best = j;
        int t = ord[i]; ord[i] = ord[best]; ord[best] = t;
    }
    for (int i = 0; i < 64; i++) g_row_order[i] = ord[i];
}

// ---------------------------------------------------------------------------
// Half-stage loader: K=32 slice of X (hi/lo) and V (hi/lo) into stage s.
// ---------------------------------------------------------------------------
__device__ __forceinline__ void load_half(uint32_t sb, int s, int n, int c, int kh,
                                          int t0, int tid)
{
    const uint32_t xh = sb + s * STAGE;
    const uint32_t xl = xh + XB;
    const uint32_t vh = xl + XB;
    const uint32_t vl = vh + VB;
    const int k0 = c * 64 + kh * 32;
    // X: 128 rows x 4 chunks (16B) x 2 arrays
    #pragma unroll
    for (int i = 0; i < 2; i++) {
        const int id = tid + i * 256;          // 0..511
        const int row = id >> 2, cb = id & 3;
        const size_t g = (size_t)(t0 + row) * KDIM + k0 + cb * 8;
        const uint32_t so = row * PITCHB + cb * 16;
        cp_async16(xh + so, g_xhi + g);
        cp_async16(xl + so, g_xlo + g);
    }
    // V: 64 rows x 4 chunks x 2 arrays
    {
        const int row = tid >> 2, cb = tid & 3;
        const size_t g = (size_t)n * 4096 + row * 64 + kh * 32 + cb * 8;
        const uint32_t so = row * PITCHB + cb * 16;
        cp_async16(vh + so, g_vhi + g);
        cp_async16(vl + so, g_vlo + g);
    }
}

// ---------------------------------------------------------------------------
// Main kernel: 256 threads = 8 warps (4 token x 2 n), warp tile 32x32,
// bf16 HMMA 3-product split, 3-stage K32 pipeline, one barrier per stage.
// ---------------------------------------------------------------------------
__global__ void __launch_bounds__(256, 2) fsl_hmma_kernel(
    const float* __restrict__ bias,
    const int*   __restrict__ bcols,
    float*       __restrict__ out)
{
    extern __shared__ char smem[];
    const uint32_t sb = smem_u32(smem);
    const int tid  = threadIdx.x;
    const int warp = tid >> 5;
    const int lane = tid & 31;
    const int slab = blockIdx.x & 15;
    const int r    = g_row_order[blockIdx.x >> 4];
    const int t0   = slab * MT;

    const int wt = (warp >> 1) * 32;
    const int wn = (warp & 1) * 32;

    const int cnt   = g_row_cnt[r];
    const int total = 2 * cnt;                 // half-block stages
    const int* list = &g_row_list[r * NBMAX];

    float acc[2][4][4];
    #pragma unroll
    for (int mi = 0; mi < 2; mi++)
        #pragma unroll
        for (int nj = 0; nj < 4; nj++)
            #pragma unroll
            for (int q = 0; q < 4; q++) acc[mi][nj][q] = 0.0f;

    // ldmatrix lane-address components
    const int a_m = (lane & 7) + ((lane >> 3) & 1) * 8;
    const int a_k = (lane >> 4) * 8;
    const int b_n = (lane & 7) + ((lane >> 4) & 1) * 8;
    const int b_k = ((lane >> 3) & 1) * 8;

    // Prologue: prime up to 2 stages
    if (total > 0) load_half(sb, 0, list[0], __ldg(&bcols[list[0]]), 0, t0, tid);
    CP_COMMIT();
    if (total > 1) load_half(sb, 1, list[0], __ldg(&bcols[list[0]]), 1, t0, tid);
    CP_COMMIT();

    for (int i = 0; i < total; i++) {
        CP_WAIT(1);
        __syncthreads();

        // Refill the stage freed two iterations ago (fully overlaps compute)
        if (i + 2 < total) {
            const int j = i + 2;
            const int n = list[j >> 1];
            load_half(sb, j % NSTG, n, __ldg(&bcols[n]), j & 1, t0, tid);
        }
        CP_COMMIT();

        const int s = i % NSTG;
        const uint32_t xh = sb + s * STAGE;
        const uint32_t xl = xh + XB;
        const uint32_t vh = xl + XB;
        const uint32_t vl = vh + VB;

        #pragma unroll
        for (int kc = 0; kc < 2; kc++) {
            uint32_t ah[2][4], al[2][4], bh[2][4], bl[2][4];
            const uint32_t ao = (wt + a_m) * PITCHB + (kc * 16 + a_k) * 2;
            const uint32_t bo = (wn + b_n) * PITCHB + (kc * 16 + b_k) * 2;
            #pragma unroll
            for (int mi = 0; mi < 2; mi++) {
                ldsm_x4(ah[mi], xh + ao + mi * 16 * PITCHB);
                ldsm_x4(al[mi], xl + ao + mi * 16 * PITCHB);
            }
            #pragma unroll
            for (int j = 0; j < 2; j++) {
                ldsm_x4(bh[j], vh + bo + j * 16 * PITCHB);
                ldsm_x4(bl[j], vl + bo + j * 16 * PITCHB);
            }
            #pragma unroll
            for (int mi = 0; mi < 2; mi++) {
                #pragma unroll
                for (int j = 0; j < 2; j++) {
                    mma_bf16(acc[mi][2 * j + 0], ah[mi], bh[j][0], bh[j][1]);
                    mma_bf16(acc[mi][2 * j + 1], ah[mi], bh[j][2], bh[j][3]);
                    mma_bf16(acc[mi][2 * j + 0], ah[mi], bl[j][0], bl[j][1]);
                    mma_bf16(acc[mi][2 * j + 1], ah[mi], bl[j][2], bl[j][3]);
                    mma_bf16(acc[mi][2 * j + 0], al[mi], bh[j][0], bh[j][1]);
                    mma_bf16(acc[mi][2 * j + 1], al[mi], bh[j][2], bh[j][3]);
                }
            }
        }
    }

    // Epilogue: bias + tanh-GELU, float2 stores.
    const int row0 = lane >> 2;
    const int cp2  = (lane & 3) * 2;
    #pragma unroll
    for (int mi = 0; mi < 2; mi++) {
        #pragma unroll
        for (int nj = 0; nj < 4; nj++) {
            const int nb = wn + nj * 8 + cp2;
            const float b0 = __ldg(&bias[r * 64 + nb]);
            const float b1 = __ldg(&bias[r * 64 + nb + 1]);
            #pragma unroll
            for (int h = 0; h < 2; h++) {
                const int m = wt + mi * 16 + row0 + h * 8;
                float2 o;
                o.x = gelu_tanh(acc[mi][nj][2 * h + 0] + b0);
                o.y = gelu_tanh(acc[mi][nj][2 * h + 1] + b1);
                *(float2*)&out[(size_t)(t0 + m) * MDIM + r * 64 + nb] = o;
            }
        }
    }
}

// ---------------------------------------------------------------------------
extern "C" void kernel_launch(void* const* d_in, const int* in_sizes, int n_in,
                              void* d_out, int out_size)
{
    const float* x      = (const float*)d_in[0];
    const float* values = (const float*)d_in[1];
    const float* bias   = (const float*)d_in[2];
    const int*   brows  = (const int*)d_in[3];
    const int*   bcols  = (const int*)d_in[4];
    float*       out    = (float*)d_out;

    const int n_blocks = in_sizes[3];
    const int x_elems  = in_sizes[0];
    const int v_elems  = in_sizes[1];

    cudaFuncSetAttribute(fsl_hmma_kernel,
                         cudaFuncAttributeMaxDynamicSharedMemorySize, SMEM_TOTAL);

    convert_split_kernel<<<2048, 256>>>(x, x_elems / 4, 0);
    convert_split_kernel<<<1024, 256>>>(values, v_elems / 4, 1);
    build_lists_kernel<<<64, 32>>>(brows, n_blocks);
    sort_rows_kernel<<<1, 1>>>();

    fsl_hmma_kernel<<<1024, 256, SMEM_TOTAL>>>(bias, bcols, out);
}

// round 6
// speedup vs baseline: 1.4847x; 1.4847x over previous
#include <cuda_runtime.h>
#include <cuda_bf16.h>
#include <cstdint>

// Shapes (fixed): x (2048,4096) fp32, values (1024,64,64) fp32, bias (4096,),
// block_rows/cols (1024,) int32 in [0,64), out (2048,4096) fp32.
#define KDIM  4096
#define MDIM  4096
#define TTOK  2048
#define NBMAX 1024
#define MT    128            // tokens per CTA
#define NT    64             // out features per CTA (one row block)

// Half-block staging: K=32 per stage, row pitch 40 bf16 = 80 B (16B multiple,
// and 80*r mod 128 distinct for r=0..7 -> ldmatrix conflict-free).
#define PITCHB  80
#define XB      (128 * PITCHB)        // 10240 per array
#define VB      (64  * PITCHB)        // 5120  per array
#define STAGE   (2 * XB + 2 * VB)     // 30720
#define NSTG    3
#define SMEM_TOTAL (NSTG * STAGE)     // 92160 -> 2 CTAs/SM

// ---- device scratch (static globals; no allocations allowed) ----
__device__ __nv_bfloat16 g_xhi[TTOK * KDIM];
__device__ __nv_bfloat16 g_xlo[TTOK * KDIM];
__device__ __nv_bfloat16 g_vhi[NBMAX * 64 * 64];
__device__ __nv_bfloat16 g_vlo[NBMAX * 64 * 64];
__device__ int g_row_list[64 * NBMAX];
__device__ int g_row_cnt[64];
__device__ int g_row_order[64];

// ---- PTX helpers (baseline sm_80+ features only) ----
__device__ __forceinline__ uint32_t smem_u32(const void* p) {
    uint32_t a;
    asm("{ .reg .u64 t; cvta.to.shared.u64 t, %1; cvt.u32.u64 %0, t; }" : "=r"(a) : "l"(p));
    return a;
}
__device__ __forceinline__ void cp_async16(uint32_t saddr, const void* gaddr) {
    asm volatile("cp.async.cg.shared.global [%0], [%1], 16;" :: "r"(saddr), "l"(gaddr));
}
#define CP_COMMIT() asm volatile("cp.async.commit_group;" ::: "memory")
#define CP_WAIT(n)  asm volatile("cp.async.wait_group %0;" :: "n"(n) : "memory")

__device__ __forceinline__ void ldsm_x4(uint32_t* r, uint32_t addr) {
    asm volatile("ldmatrix.sync.aligned.m8n8.x4.shared.b16 {%0,%1,%2,%3}, [%4];"
                 : "=r"(r[0]), "=r"(r[1]), "=r"(r[2]), "=r"(r[3]) : "r"(addr));
}
__device__ __forceinline__ void mma_bf16(float* d, const uint32_t* a, uint32_t b0, uint32_t b1) {
    asm volatile(
        "mma.sync.aligned.m16n8k16.row.col.f32.bf16.bf16.f32 "
        "{%0,%1,%2,%3}, {%4,%5,%6,%7}, {%8,%9}, {%0,%1,%2,%3};"
        : "+f"(d[0]), "+f"(d[1]), "+f"(d[2]), "+f"(d[3])
        : "r"(a[0]), "r"(a[1]), "r"(a[2]), "r"(a[3]), "r"(b0), "r"(b1));
}

__device__ __forceinline__ float gelu_tanh(float v) {
    float inner = 0.7978845608f * (v + 0.044715f * v * v * v);
    return 0.5f * v * (1.0f + tanhf(inner));
}

// ---------------------------------------------------------------------------
// Pre-pass 1: fp32 -> bf16 hi/lo split (which=0 -> x, 1 -> values)
// ---------------------------------------------------------------------------
__global__ void __launch_bounds__(256) convert_split_kernel(
    const float* __restrict__ src, int n4, int which)
{
    uint2* h2 = (uint2*)(which ? g_vhi : g_xhi);
    uint2* l2 = (uint2*)(which ? g_vlo : g_xlo);
    const float4* s4 = (const float4*)src;
    int stride = gridDim.x * blockDim.x;
    for (int i = blockIdx.x * blockDim.x + threadIdx.x; i < n4; i += stride) {
        float4 v = s4[i];
        __nv_bfloat16 hx = __float2bfloat16_rn(v.x);
        __nv_bfloat16 hy = __float2bfloat16_rn(v.y);
        __nv_bfloat16 hz = __float2bfloat16_rn(v.z);
        __nv_bfloat16 hw = __float2bfloat16_rn(v.w);
        __nv_bfloat16 lx = __float2bfloat16_rn(v.x - __bfloat162float(hx));
        __nv_bfloat16 ly = __float2bfloat16_rn(v.y - __bfloat162float(hy));
        __nv_bfloat16 lz = __float2bfloat16_rn(v.z - __bfloat162float(hz));
        __nv_bfloat16 lw = __float2bfloat16_rn(v.w - __bfloat162float(hw));
        __nv_bfloat162 p0{hx, hy}, p1{hz, hw}, q0{lx, ly}, q1{lz, lw};
        uint2 H{*(uint32_t*)&p0, *(uint32_t*)&p1};
        uint2 L{*(uint32_t*)&q0, *(uint32_t*)&q1};
        h2[i] = H;
        l2[i] = L;
    }
}

// ---------------------------------------------------------------------------
// Pre-pass 2: per-row compacted block lists (stable order -> deterministic)
// ---------------------------------------------------------------------------
__global__ void __launch_bounds__(32) build_lists_kernel(
    const int* __restrict__ brows, int nb)
{
    int r = blockIdx.x, lane = threadIdx.x, cnt = 0;
    for (int base = 0; base < nb; base += 32) {
        int n = base + lane;
        int row = (n < nb) ? brows[n] : -1;
        unsigned m = __ballot_sync(0xFFFFFFFFu, row == r);
        if (row == r)
            g_row_list[r * NBMAX + cnt + __popc(m & ((1u << lane) - 1u))] = n;
        cnt += __popc(m);
    }
    if (lane == 0) g_row_cnt[r] = cnt;
}

// ---------------------------------------------------------------------------
// Pre-pass 3: LPT order via parallel rank (64 threads, deterministic).
// rank(i) = #{ j : cnt[j] > cnt[i] or (cnt[j]==cnt[i] and j < i) }
// ---------------------------------------------------------------------------
__global__ void __launch_bounds__(64) order_rows_kernel()
{
    __shared__ int cnts[64];
    const int i = threadIdx.x;
    cnts[i] = g_row_cnt[i];
    __syncthreads();
    const int c = cnts[i];
    int rank = 0;
    #pragma unroll
    for (int j = 0; j < 64; j++) {
        const int cj = cnts[j];
        rank += (cj > c) || (cj == c && j < i);
    }
    g_row_order[rank] = i;
}

// ---------------------------------------------------------------------------
// Half-stage loader: K=32 slice of X (hi/lo) and V (hi/lo) into stage s.
// ---------------------------------------------------------------------------
__device__ __forceinline__ void load_half(uint32_t sb, int s, int n, int c, int kh,
                                          int t0, int tid)
{
    const uint32_t xh = sb + s * STAGE;
    const uint32_t xl = xh + XB;
    const uint32_t vh = xl + XB;
    const uint32_t vl = vh + VB;
    const int k0 = c * 64 + kh * 32;
    // X: 128 rows x 4 chunks (16B) x 2 arrays
    #pragma unroll
    for (int i = 0; i < 2; i++) {
        const int id = tid + i * 256;          // 0..511
        const int row = id >> 2, cb = id & 3;
        const size_t g = (size_t)(t0 + row) * KDIM + k0 + cb * 8;
        const uint32_t so = row * PITCHB + cb * 16;
        cp_async16(xh + so, g_xhi + g);
        cp_async16(xl + so, g_xlo + g);
    }
    // V: 64 rows x 4 chunks x 2 arrays
    {
        const int row = tid >> 2, cb = tid & 3;
        const size_t g = (size_t)n * 4096 + row * 64 + kh * 32 + cb * 8;
        const uint32_t so = row * PITCHB + cb * 16;
        cp_async16(vh + so, g_vhi + g);
        cp_async16(vl + so, g_vlo + g);
    }
}

// ---------------------------------------------------------------------------
// Main kernel: 256 threads = 8 warps (4 token x 2 n), warp tile 32x32,
// bf16 HMMA 3-product split, 3-stage K32 pipeline, one barrier per stage.
// MMAs grouped by split-term: 8 independent HMMAs per pass, accumulator
// reuse distance = 8 (hides HMMA latency).
// ---------------------------------------------------------------------------
__global__ void __launch_bounds__(256, 2) fsl_hmma_kernel(
    const float* __restrict__ bias,
    const int*   __restrict__ bcols,
    float*       __restrict__ out)
{
    extern __shared__ char smem[];
    const uint32_t sb = smem_u32(smem);
    const int tid  = threadIdx.x;
    const int warp = tid >> 5;
    const int lane = tid & 31;
    const int slab = blockIdx.x & 15;
    const int r    = g_row_order[blockIdx.x >> 4];
    const int t0   = slab * MT;

    const int wt = (warp >> 1) * 32;
    const int wn = (warp & 1) * 32;

    const int cnt   = g_row_cnt[r];
    const int total = 2 * cnt;                 // half-block stages
    const int* list = &g_row_list[r * NBMAX];

    float acc[2][4][4];
    #pragma unroll
    for (int mi = 0; mi < 2; mi++)
        #pragma unroll
        for (int nj = 0; nj < 4; nj++)
            #pragma unroll
            for (int q = 0; q < 4; q++) acc[mi][nj][q] = 0.0f;

    // ldmatrix lane-address components
    const int a_m = (lane & 7) + ((lane >> 3) & 1) * 8;
    const int a_k = (lane >> 4) * 8;
    const int b_n = (lane & 7) + ((lane >> 4) & 1) * 8;
    const int b_k = ((lane >> 3) & 1) * 8;

    // Prologue: prime up to 2 stages
    if (total > 0) load_half(sb, 0, list[0], __ldg(&bcols[list[0]]), 0, t0, tid);
    CP_COMMIT();
    if (total > 1) load_half(sb, 1, list[0], __ldg(&bcols[list[0]]), 1, t0, tid);
    CP_COMMIT();

    for (int i = 0; i < total; i++) {
        CP_WAIT(1);
        __syncthreads();

        // Refill the stage freed two iterations ago (fully overlaps compute)
        if (i + 2 < total) {
            const int j = i + 2;
            const int n = list[j >> 1];
            load_half(sb, j % NSTG, n, __ldg(&bcols[n]), j & 1, t0, tid);
        }
        CP_COMMIT();

        const int s = i % NSTG;
        const uint32_t xh = sb + s * STAGE;
        const uint32_t xl = xh + XB;
        const uint32_t vh = xl + XB;
        const uint32_t vl = vh + VB;

        #pragma unroll
        for (int kc = 0; kc < 2; kc++) {
            uint32_t ah[2][4], al[2][4], bh[2][4], bl[2][4];
            const uint32_t ao = (wt + a_m) * PITCHB + (kc * 16 + a_k) * 2;
            const uint32_t bo = (wn + b_n) * PITCHB + (kc * 16 + b_k) * 2;
            #pragma unroll
            for (int mi = 0; mi < 2; mi++) {
                ldsm_x4(ah[mi], xh + ao + mi * 16 * PITCHB);
                ldsm_x4(al[mi], xl + ao + mi * 16 * PITCHB);
            }
            #pragma unroll
            for (int j = 0; j < 2; j++) {
                ldsm_x4(bh[j], vh + bo + j * 16 * PITCHB);
                ldsm_x4(bl[j], vl + bo + j * 16 * PITCHB);
            }
            // Pass 1: hi*hi (8 independent MMAs)
            #pragma unroll
            for (int mi = 0; mi < 2; mi++)
                #pragma unroll
                for (int j = 0; j < 2; j++) {
                    mma_bf16(acc[mi][2 * j + 0], ah[mi], bh[j][0], bh[j][1]);
                    mma_bf16(acc[mi][2 * j + 1], ah[mi], bh[j][2], bh[j][3]);
                }
            // Pass 2: hi*lo
            #pragma unroll
            for (int mi = 0; mi < 2; mi++)
                #pragma unroll
                for (int j = 0; j < 2; j++) {
                    mma_bf16(acc[mi][2 * j + 0], ah[mi], bl[j][0], bl[j][1]);
                    mma_bf16(acc[mi][2 * j + 1], ah[mi], bl[j][2], bl[j][3]);
                }
            // Pass 3: lo*hi
            #pragma unroll
            for (int mi = 0; mi < 2; mi++)
                #pragma unroll
                for (int j = 0; j < 2; j++) {
                    mma_bf16(acc[mi][2 * j + 0], al[mi], bh[j][0], bh[j][1]);
                    mma_bf16(acc[mi][2 * j + 1], al[mi], bh[j][2], bh[j][3]);
                }
        }
    }

    // Epilogue: bias + tanh-GELU, float2 stores.
    const int row0 = lane >> 2;
    const int cp2  = (lane & 3) * 2;
    #pragma unroll
    for (int mi = 0; mi < 2; mi++) {
        #pragma unroll
        for (int nj = 0; nj < 4; nj++) {
            const int nb = wn + nj * 8 + cp2;
            const float b0 = __ldg(&bias[r * 64 + nb]);
            const float b1 = __ldg(&bias[r * 64 + nb + 1]);
            #pragma unroll
            for (int h = 0; h < 2; h++) {
                const int m = wt + mi * 16 + row0 + h * 8;
                float2 o;
                o.x = gelu_tanh(acc[mi][nj][2 * h + 0] + b0);
                o.y = gelu_tanh(acc[mi][nj][2 * h + 1] + b1);
                *(float2*)&out[(size_t)(t0 + m) * MDIM + r * 64 + nb] = o;
            }
        }
    }
}

// ---------------------------------------------------------------------------
extern "C" void kernel_launch(void* const* d_in, const int* in_sizes, int n_in,
                              void* d_out, int out_size)
{
    const float* x      = (const float*)d_in[0];
    const float* values = (const float*)d_in[1];
    const float* bias   = (const float*)d_in[2];
    const int*   brows  = (const int*)d_in[3];
    const int*   bcols  = (const int*)d_in[4];
    float*       out    = (float*)d_out;

    const int n_blocks = in_sizes[3];
    const int x_elems  = in_sizes[0];
    const int v_elems  = in_sizes[1];

    cudaFuncSetAttribute(fsl_hmma_kernel,
                         cudaFuncAttributeMaxDynamicSharedMemorySize, SMEM_TOTAL);

    convert_split_kernel<<<2048, 256>>>(x, x_elems / 4, 0);
    convert_split_kernel<<<1024, 256>>>(values, v_elems / 4, 1);
    build_lists_kernel<<<64, 32>>>(brows, n_blocks);
    order_rows_kernel<<<1, 64>>>();

    fsl_hmma_kernel<<<1024, 256, SMEM_TOTAL>>>(bias, bcols, out);
}

// round 9
// speedup vs baseline: 2.9780x; 2.0058x over previous
#include <cuda_runtime.h>
#include <cuda_fp16.h>
#include <cstdint>

// Shapes (fixed): x (2048,4096) fp32, values (1024,64,64) fp32, bias (4096,),
// block_rows/cols (1024,) int32 in [0,64), out (2048,4096) fp32.
#define KDIM  4096
#define MDIM  4096
#define TTOK  2048
#define NBMAX 1024
#define MT    128            // tokens per CTA
#define NT    64             // out features per CTA (one row block)

// Half-block staging: K=32 per stage, row pitch 40 fp16 = 80 B (16B multiple,
// 80*r mod 128 distinct for r=0..7 -> ldmatrix conflict-free).
#define PITCHB  80
#define XB      (128 * PITCHB)        // 10240
#define VB      (64  * PITCHB)        // 5120
#define STAGE   (XB + VB)             // 15360
#define NSTG    4
#define SMEM_TOTAL (NSTG * STAGE)     // 61440 -> 3 CTAs/SM

// ---- device scratch (static globals; no allocations allowed) ----
__device__ __half g_xh[TTOK * KDIM];          // 16 MB
__device__ __half g_vh[NBMAX * 64 * 64];      // 8 MB
__device__ int g_row_list[64 * NBMAX];
__device__ int g_row_cnt[64];
__device__ int g_row_order[64];

// ---- PTX helpers (baseline sm_80+ features only) ----
__device__ __forceinline__ uint32_t smem_u32(const void* p) {
    uint32_t a;
    asm("{ .reg .u64 t; cvta.to.shared.u64 t, %1; cvt.u32.u64 %0, t; }" : "=r"(a) : "l"(p));
    return a;
}
__device__ __forceinline__ void cp_async16(uint32_t saddr, const void* gaddr) {
    asm volatile("cp.async.cg.shared.global [%0], [%1], 16;" :: "r"(saddr), "l"(gaddr));
}
#define CP_COMMIT() asm volatile("cp.async.commit_group;" ::: "memory")
#define CP_WAIT(n)  asm volatile("cp.async.wait_group %0;" :: "n"(n) : "memory")

__device__ __forceinline__ void ldsm_x4(uint32_t* r, uint32_t addr) {
    asm volatile("ldmatrix.sync.aligned.m8n8.x4.shared.b16 {%0,%1,%2,%3}, [%4];"
                 : "=r"(r[0]), "=r"(r[1]), "=r"(r[2]), "=r"(r[3]) : "r"(addr));
}
__device__ __forceinline__ void mma_f16(float* d, const uint32_t* a, uint32_t b0, uint32_t b1) {
    asm volatile(
        "mma.sync.aligned.m16n8k16.row.col.f32.f16.f16.f32 "
        "{%0,%1,%2,%3}, {%4,%5,%6,%7}, {%8,%9}, {%0,%1,%2,%3};"
        : "+f"(d[0]), "+f"(d[1]), "+f"(d[2]), "+f"(d[3])
        : "r"(a[0]), "r"(a[1]), "r"(a[2]), "r"(a[3]), "r"(b0), "r"(b1));
}

__device__ __forceinline__ float gelu_tanh(float v) {
    float inner = 0.7978845608f * (v + 0.044715f * v * v * v);
    return 0.5f * v * (1.0f + tanhf(inner));
}

// ---------------------------------------------------------------------------
// Pre-pass 1: fp32 -> fp16 convert (which=0 -> x, 1 -> values)
// ---------------------------------------------------------------------------
__global__ void __launch_bounds__(256) convert_kernel(
    const float* __restrict__ src, int n4, int which)
{
    uint2* dst = (uint2*)(which ? g_vh : g_xh);
    const float4* s4 = (const float4*)src;
    int stride = gridDim.x * blockDim.x;
    for (int i = blockIdx.x * blockDim.x + threadIdx.x; i < n4; i += stride) {
        float4 v = s4[i];
        __half2 a = __floats2half2_rn(v.x, v.y);
        __half2 b = __floats2half2_rn(v.z, v.w);
        uint2 o{*(uint32_t*)&a, *(uint32_t*)&b};
        dst[i] = o;
    }
}

// ---------------------------------------------------------------------------
// Pre-pass 2: per-row compacted block lists (stable order -> deterministic)
// ---------------------------------------------------------------------------
__global__ void __launch_bounds__(32) build_lists_kernel(
    const int* __restrict__ brows, int nb)
{
    int r = blockIdx.x, lane = threadIdx.x, cnt = 0;
    for (int base = 0; base < nb; base += 32) {
        int n = base + lane;
        int row = (n < nb) ? brows[n] : -1;
        unsigned m = __ballot_sync(0xFFFFFFFFu, row == r);
        if (row == r)
            g_row_list[r * NBMAX + cnt + __popc(m & ((1u << lane) - 1u))] = n;
        cnt += __popc(m);
    }
    if (lane == 0) g_row_cnt[r] = cnt;
}

// ---------------------------------------------------------------------------
// Pre-pass 3: LPT order via parallel rank (deterministic).
// ---------------------------------------------------------------------------
__global__ void __launch_bounds__(64) order_rows_kernel()
{
    __shared__ int cnts[64];
    const int i = threadIdx.x;
    cnts[i] = g_row_cnt[i];
    __syncthreads();
    const int c = cnts[i];
    int rank = 0;
    #pragma unroll
    for (int j = 0; j < 64; j++) {
        const int cj = cnts[j];
        rank += (cj > c) || (cj == c && j < i);
    }
    g_row_order[rank] = i;
}

// ---------------------------------------------------------------------------
// Half-stage loader: K=32 slice of X and V into stage s. 3 cp.async/thread.
// ---------------------------------------------------------------------------
__device__ __forceinline__ void load_half(uint32_t sb, int s, int n, int c, int kh,
                                          int t0, int tid)
{
    const uint32_t xs = sb + s * STAGE;
    const uint32_t vs = xs + XB;
    const int k0 = c * 64 + kh * 32;
    // X: 128 rows x 4 chunks (16B) = 512 chunks
    #pragma unroll
    for (int i = 0; i < 2; i++) {
        const int id = tid + i * 256;
        const int row = id >> 2, cb = id & 3;
        const size_t g = (size_t)(t0 + row) * KDIM + k0 + cb * 8;
        cp_async16(xs + row * PITCHB + cb * 16, g_xh + g);
    }
    // V: 64 rows x 4 chunks = 256 chunks
    {
        const int row = tid >> 2, cb = tid & 3;
        const size_t g = (size_t)n * 4096 + row * 64 + kh * 32 + cb * 8;
        cp_async16(vs + row * PITCHB + cb * 16, g_vh + g);
    }
}

// ---------------------------------------------------------------------------
// Main kernel: 256 threads = 8 warps (4 token x 2 n), warp tile 32x32,
// single-product fp16 HMMA, fp32 accum, 4-stage K32 cp.async pipeline.
// ---------------------------------------------------------------------------
__global__ void __launch_bounds__(256, 3) fsl_hmma_kernel(
    const float* __restrict__ bias,
    const int*   __restrict__ bcols,
    float*       __restrict__ out)
{
    extern __shared__ char smem[];
    const uint32_t sb = smem_u32(smem);
    const int tid  = threadIdx.x;
    const int warp = tid >> 5;
    const int lane = tid & 31;
    const int slab = blockIdx.x & 15;
    const int r    = g_row_order[blockIdx.x >> 4];
    const int t0   = slab * MT;

    const int wt = (warp >> 1) * 32;
    const int wn = (warp & 1) * 32;

    const int cnt   = g_row_cnt[r];
    const int total = 2 * cnt;                 // half-block stages
    const int* list = &g_row_list[r * NBMAX];

    float acc[2][4][4];
    #pragma unroll
    for (int mi = 0; mi < 2; mi++)
        #pragma unroll
        for (int nj = 0; nj < 4; nj++)
            #pragma unroll
            for (int q = 0; q < 4; q++) acc[mi][nj][q] = 0.0f;

    // ldmatrix lane-address components (mapping validated in R4-R6)
    const int a_m = (lane & 7) + ((lane >> 3) & 1) * 8;
    const int a_k = (lane >> 4) * 8;
    const int b_n = (lane & 7) + ((lane >> 4) & 1) * 8;
    const int b_k = ((lane >> 3) & 1) * 8;

    // Prologue: prime 3 of 4 stages. Stage j = block list[j>>1], half j&1.
    #pragma unroll
    for (int j = 0; j < 3; j++) {
        if (j < total) {
            const int n = list[j >> 1];
            load_half(sb, j, n, __ldg(&bcols[n]), j & 1, t0, tid);
        }
        CP_COMMIT();
    }

    for (int i = 0; i < total; i++) {
        CP_WAIT(2);
        __syncthreads();

        // Refill the stage freed last iteration (overlaps compute)
        if (i + 3 < total) {
            const int j = i + 3;
            const int n = list[j >> 1];
            load_half(sb, (i + 3) & 3, n, __ldg(&bcols[n]), j & 1, t0, tid);
        }
        CP_COMMIT();

        const uint32_t xs = sb + (i & 3) * STAGE;
        const uint32_t vs = xs + XB;

        #pragma unroll
        for (int kc = 0; kc < 2; kc++) {
            uint32_t ah[2][4], bh[2][4];
            const uint32_t ao = (wt + a_m) * PITCHB + (kc * 16 + a_k) * 2;
            const uint32_t bo = (wn + b_n) * PITCHB + (kc * 16 + b_k) * 2;
            #pragma unroll
            for (int mi = 0; mi < 2; mi++)
                ldsm_x4(ah[mi], xs + ao + mi * 16 * PITCHB);
            #pragma unroll
            for (int j = 0; j < 2; j++)
                ldsm_x4(bh[j], vs + bo + j * 16 * PITCHB);
            #pragma unroll
            for (int mi = 0; mi < 2; mi++)
                #pragma unroll
                for (int j = 0; j < 2; j++) {
                    mma_f16(acc[mi][2 * j + 0], ah[mi], bh[j][0], bh[j][1]);
                    mma_f16(acc[mi][2 * j + 1], ah[mi], bh[j][2], bh[j][3]);
                }
        }
    }

    // Epilogue: bias + tanh-GELU, float2 stores.
    const int row0 = lane >> 2;
    const int cp2  = (lane & 3) * 2;
    #pragma unroll
    for (int mi = 0; mi < 2; mi++) {
        #pragma unroll
        for (int nj = 0; nj < 4; nj++) {
            const int nb = wn + nj * 8 + cp2;
            const float b0 = __ldg(&bias[r * 64 + nb]);
            const float b1 = __ldg(&bias[r * 64 + nb + 1]);
            #pragma unroll
            for (int h = 0; h < 2; h++) {
                const int m = wt + mi * 16 + row0 + h * 8;
                float2 o;
                o.x = gelu_tanh(acc[mi][nj][2 * h + 0] + b0);
                o.y = gelu_tanh(acc[mi][nj][2 * h + 1] + b1);
                *(float2*)&out[(size_t)(t0 + m) * MDIM + r * 64 + nb] = o;
            }
        }
    }
}

// ---------------------------------------------------------------------------
extern "C" void kernel_launch(void* const* d_in, const int* in_sizes, int n_in,
                              void* d_out, int out_size)
{
    const float* x      = (const float*)d_in[0];
    const float* values = (const float*)d_in[1];
    const float* bias   = (const float*)d_in[2];
    const int*   brows  = (const int*)d_in[3];
    const int*   bcols  = (const int*)d_in[4];
    float*       out    = (float*)d_out;

    const int n_blocks = in_sizes[3];
    const int x_elems  = in_sizes[0];
    const int v_elems  = in_sizes[1];

    cudaFuncSetAttribute(fsl_hmma_kernel,
                         cudaFuncAttributeMaxDynamicSharedMemorySize, SMEM_TOTAL);

    convert_kernel<<<2048, 256>>>(x, x_elems / 4, 0);
    convert_kernel<<<1024, 256>>>(values, v_elems / 4, 1);
    build_lists_kernel<<<64, 32>>>(brows, n_blocks);
    order_rows_kernel<<<1, 64>>>();

    fsl_hmma_kernel<<<1024, 256, SMEM_TOTAL>>>(bias, bcols, out);
}